// round 7
// baseline (speedup 1.0000x reference)
#include <cuda_runtime.h>

// LIF scan — fused chain + overlapped block replay.
// B=16, S=256, H=128, N=64.  T = S*H = 32768 steps per (b,n) chain.
//
// Grid = 32 chain CTAs (blockIdx 0..31) + 1024 output CTAs, one launch.
//  * Chain CTA (b, half): warp0 runs the serial recurrence reading x from
//    a smem double buffer (warp1 prefetches 8-row blocks). It publishes the
//    TRUE carried state entering each 8-row block (32 checkpoints/chain)
//    with a release fence + per-(block,grp) flag.
//  * Output CTA (sblk, grp): spin-waits (nanosleep) for its flag, then
//    replays its 1024 steps from the exact checkpoint and streams outs +
//    synthesized spikes through a smem transpose for coalesced 512B stores.
//  A tiny reset kernel clears the flags first (they persist across graph
//  replays; stream order makes reset -> fused safe).
//
// Chain step (bit-identical to reference order; carried v = post-add acc):
//   t = v + x      (FADD, parallel)        |  FSETP(v) -> FSEL = 8 cyc
//   p = (v <= thr) (FSETP)                 |  pred-as-data path
//   v' = p ? t : x (FSEL; fl(0+x) == x)    |
// Output step (replay, proven R4/R6 form):
//   m = (v<=thr)?1:0 ; v = fma(v,m,x) ; g = (v>thr)?1:0 ; out = v*g
// Both produce identical value sequences (fma(v,1,x)==fl(v+x), fma(v,0,x)==x).

#define BB 16
#define SS 256
#define HH 128
#define NN 64
#define TT (SS * HH)

#define BLKROWS 8
#define NBLK (SS / BLKROWS)      // 32
#define ROWPAD 132
#define NGRP 32                  // (b, neuron-half)
#define NCHAIN NGRP              // chain CTAs
#define CHUNKS (BLKROWS * (HH / 4))   // 256 float4 per 8-row block

static const size_t BSNH = (size_t)BB * SS * NN * HH;

__device__ float g_chk[NBLK][BB][NN];
__device__ int   g_flag[NBLK][NGRP];

__device__ __forceinline__ float set_le(float a, float b) {
    float r; asm("set.le.f32.f32 %0, %1, %2;" : "=f"(r) : "f"(a), "f"(b)); return r;
}

#define OUT_STEP(XC, OC) do {               \
    float _m = set_le(v, thr);              \
    v = __fmaf_rn(v, _m, (XC));             \
    (OC) = (v > thr) ? v : 0.0f;            \
} while (0)

__global__ void lif_reset()
{
    int i = threadIdx.x;
    if (i < NBLK * NGRP) ((int*)g_flag)[i] = 0;
}

__global__ void __launch_bounds__(64, 1)
lif_fused(const float* __restrict__ x,       // [B, S, H]
          const float* __restrict__ thresh,  // [N]
          const float* __restrict__ acc0,    // [B, N]
          float* __restrict__ outbuf,        // outs | spikes
          int write_spikes)
{
    // Shared region (union of the two roles):
    //   chain CTA:  xsh double buffer, 2 * (1024 + 4) floats
    //   output CTA: sbuf staging,      2 * 32 * ROWPAD  floats
    __shared__ float smem_raw[2 * 32 * ROWPAD];

    const int tid  = threadIdx.x;
    const int lane = tid & 31;

    if (blockIdx.x < NCHAIN) {
        // ================== CHAIN CTA ==================
        const int grp  = blockIdx.x;
        const int b    = grp >> 1;
        const int half = grp & 1;
        const int wid  = tid >> 5;

        float (*xsh)[BLKROWS * HH + 4] = (float (*)[BLKROWS * HH + 4])smem_raw;
        const float4* __restrict__ xg = (const float4*)(x + (size_t)b * TT);

        if (wid == 1) {                       // preload block 0
            #pragma unroll
            for (int i = lane; i < CHUNKS; i += 32)
                ((float4*)xsh[0])[i] = xg[i];
        }
        __syncthreads();

        if (wid == 0) {
            const int n = half * 32 + lane;
            const float thr = thresh[n];
            float v = acc0[b * NN + n];

            for (int blk = 0; blk < NBLK; ++blk) {
                // Publish checkpoint (state entering block blk), release.
                g_chk[blk][b][n] = v;
                __threadfence();
                if (lane == 0) g_flag[blk][grp] = 1;

                const float4* xs4 = (const float4*)xsh[blk & 1];
                float4 xv = xs4[0];
                #pragma unroll 8
                for (int q = 0; q < CHUNKS; ++q) {
                    float4 xn = xs4[q + 1];   // pad-covered overread
                    // FSETP -> FSEL chain, FADD in parallel.
                    { float t = v + xv.x; bool p = (v <= thr); v = p ? t : xv.x; }
                    { float t = v + xv.y; bool p = (v <= thr); v = p ? t : xv.y; }
                    { float t = v + xv.z; bool p = (v <= thr); v = p ? t : xv.z; }
                    { float t = v + xv.w; bool p = (v <= thr); v = p ? t : xv.w; }
                    xv = xn;
                }
                __syncthreads();              // block consumed; next staged
            }
        } else {
            for (int blk = 0; blk < NBLK; ++blk) {
                if (blk + 1 < NBLK) {
                    const float4* src = xg + (size_t)(blk + 1) * CHUNKS;
                    float4* dst = (float4*)xsh[(blk + 1) & 1];
                    #pragma unroll
                    for (int i = lane; i < CHUNKS; i += 32)
                        dst[i] = src[i];
                }
                __syncthreads();
            }
        }
    } else {
        // ================== OUTPUT CTA ==================
        const int cidx = blockIdx.x - NCHAIN;
        const int grp  = cidx & (NGRP - 1);   // low bits: grp (spreads grps)
        const int sblk = cidx >> 5;           // high bits: block (low first)
        const int b    = grp >> 1;
        const int n0   = (grp & 1) * 32;
        const int s0   = sblk * BLKROWS;

        float (*sbuf)[32 * ROWPAD] = (float (*)[32 * ROWPAD])smem_raw;

        // Wait for this block's checkpoint (acquire).
        if (tid == 0) {
            const volatile int* f = &g_flag[sblk][grp];
            while (*f == 0) __nanosleep(128);
        }
        __syncthreads();
        __threadfence();

        if (tid < 32) {
            // -------- producer: exact replay from checkpoint --------
            const int n = n0 + lane;
            const float thr = thresh[n];
            float v = g_chk[sblk][b][n];

            const float4* __restrict__ xp =
                (const float4*)(x + (size_t)b * TT + (size_t)s0 * HH);

            float* const row0 = &sbuf[0][lane * ROWPAD];
            float* const row1 = &sbuf[1][lane * ROWPAD];

            for (int r = 0; r < BLKROWS; ++r) {
                float* rw = (r & 1) ? row1 : row0;
                const float4* xrow = xp + r * (HH / 4);
                #pragma unroll 8
                for (int q = 0; q < HH / 4; ++q) {
                    float4 xv = xrow[q];      // broadcast LDG (L2-hot)
                    float4 o;
                    OUT_STEP(xv.x, o.x); OUT_STEP(xv.y, o.y);
                    OUT_STEP(xv.z, o.z); OUT_STEP(xv.w, o.w);
                    *(float4*)&rw[q * 4] = o;
                }
                __syncthreads();
            }
        } else {
            // -------- flusher: transpose + spikes --------
            const int fl = tid - 32;
            float* __restrict__ outp = outbuf;
            float* __restrict__ spkp = outbuf + BSNH;

            for (int r = 0; r < BLKROWS; ++r) {
                __syncthreads();
                const float* buf = sbuf[r & 1];
                const int s = s0 + r;
                size_t base = (((size_t)b * SS + s) * NN + n0) * HH + fl * 4;
                #pragma unroll 4
                for (int rr = 0; rr < 32; ++rr) {
                    float4 vv = *(const float4*)&buf[rr * ROWPAD + fl * 4];
                    *(float4*)&outp[base + (size_t)rr * HH] = vv;
                    if (write_spikes) {
                        float4 sp;
                        sp.x = (vv.x > 0.0f) ? 1.0f : 0.0f;
                        sp.y = (vv.y > 0.0f) ? 1.0f : 0.0f;
                        sp.z = (vv.z > 0.0f) ? 1.0f : 0.0f;
                        sp.w = (vv.w > 0.0f) ? 1.0f : 0.0f;
                        *(float4*)&spkp[base + (size_t)rr * HH] = sp;
                    }
                }
            }
        }
    }
}

extern "C" void kernel_launch(void* const* d_in, const int* in_sizes, int n_in,
                              void* d_out, int out_size)
{
    const float* x      = (const float*)d_in[0];  // [16, 256, 128] f32
    const float* thresh = (const float*)d_in[1];  // [64] f32
    const float* acc0   = (const float*)d_in[2];  // [16, 64] f32
    float* out = (float*)d_out;

    int write_spikes = ((size_t)out_size >= 2 * BSNH) ? 1 : 0;

    lif_reset<<<1, 1024>>>();
    lif_fused<<<NCHAIN + NGRP * NBLK, 64>>>(x, thresh, acc0, out, write_spikes);
}